// round 13
// baseline (speedup 1.0000x reference)
#include <cuda_runtime.h>
#include <math.h>

#define BB 64
#define SS 512
#define HH 768
#define LL 9

// scratch (no allocations allowed in kernel_launch)
__device__ int   g_src[BB * SS];   // g_src[b*SS + p] = source token s for compacted slot p
__device__ int   g_cnt[BB];        // valid tokens per row
__device__ float g_sb[LL];         // softmax(bias) for tail slots
__device__ float g_Wt[LL * HH];    // W transposed: g_Wt[j*HH + k] = W[k*LL + j]

// ---------------------------------------------------------------------------
// Kernel 1: per-row ballot scan -> gather idx + count; transposes a slice of
// W into g_Wt; precomputes softmax(bias). NO tail fill (main kernel does it).
// ---------------------------------------------------------------------------
__global__ void __launch_bounds__(SS) ner_scan_kernel(const int* __restrict__ mask,
                                                      const float* __restrict__ W,
                                                      const float* __restrict__ bias) {
    __shared__ int wsum[16];
    const int b    = blockIdx.x;
    const int s    = threadIdx.x;
    const int lane = s & 31;
    const int wid  = s >> 5;
    const int m    = mask[b * SS + s];
    const unsigned bal = __ballot_sync(0xffffffffu, m != 0);
    const int pre  = __popc(bal & ((1u << lane) - 1u));
    if (lane == 31) wsum[wid] = __popc(bal);

    // transpose a 108-element slice of W (64 blocks x 108 = 6912 = LL*HH)
    if (s < 108) {
        const int idx = b * 108 + s;
        const int k = idx / LL;
        const int j = idx - k * LL;
        g_Wt[j * HH + k] = W[idx];
    }

    __syncthreads();
    if (wid == 0 && lane < 16) {
        int v = wsum[lane];
#pragma unroll
        for (int off = 1; off < 16; off <<= 1) {
            int u = __shfl_up_sync(0xffffu, v, off);
            if (lane >= off) v += u;
        }
        wsum[lane] = v;   // inclusive scan of warp sums
    }
    __syncthreads();
    const int offset = wid ? wsum[wid - 1] : 0;
    if (m) g_src[b * SS + offset + pre] = s;
    if (s == 0) g_cnt[b] = wsum[15];

    if (b == 0 && s == 0) {
        float t[LL];
        float mx = -1e30f;
#pragma unroll
        for (int j = 0; j < LL; j++) { t[j] = bias[j]; mx = fmaxf(mx, t[j]); }
        float sum = 0.f;
#pragma unroll
        for (int j = 0; j < LL; j++) { t[j] = __expf(t[j] - mx); sum += t[j]; }
        const float inv = 1.f / sum;
#pragma unroll
        for (int j = 0; j < LL; j++) g_sb[j] = t[j] * inv;
    }
}

// ---------------------------------------------------------------------------
// Kernel 2: 32 slots/block (one row), 8 warps x 4 tokens/warp.
// Dead blocks write their tail slots and exit fast; live blocks copy W^T to
// smem and run the prefetched FMA loop. __launch_bounds__(256,3) targets
// <=85 regs -> 3 blocks/SM = 24 warps/SM.
// ---------------------------------------------------------------------------
__global__ void __launch_bounds__(256, 3) ner_main_kernel(const float* __restrict__ X,
                                                          const float* __restrict__ bias,
                                                          float* __restrict__ out) {
    const int tid  = threadIdx.x;
    const int lane = tid & 31;
    const int tb   = blockIdx.x * 32;
    const int bi   = tb >> 9;            // SS = 512
    const int pb   = tb & (SS - 1);
    const int cnt  = g_cnt[bi];

    if (pb >= cnt) {                     // whole block is tail (block-uniform)
        // write softmax(bias) to all 32*9 = 288 floats of this block's slots
        float* base = out + (size_t)tb * LL;
        for (int i = tid; i < 32 * LL; i += 256) base[i] = g_sb[i % LL];
        return;
    }

    __shared__ float sWt[LL * HH];
    __shared__ float sB[LL];
    {
        const float4* src = (const float4*)g_Wt;
        float4* dst = (float4*)sWt;
        for (int i = tid; i < (LL * HH) / 4; i += 256) dst[i] = src[i];
        if (tid < LL) sB[tid] = bias[tid];
    }
    __syncthreads();

    const int warp = tid >> 5;
    const int t0   = tb + warp * 4;
    const int p0   = t0 & (SS - 1);

    if (p0 >= cnt) {                     // tail warp in a mixed block
        float* base = out + (size_t)t0 * LL;
        for (int i = lane; i < 4 * LL; i += 32) base[i] = g_sb[i % LL];
        return;
    }

    const int nv = min(4, cnt - p0);
    const float4* xp[4];
#pragma unroll
    for (int i = 0; i < 4; i++) {
        const int pi = p0 + ((i < nv) ? i : 0);   // clamp (tail writes handled below)
        xp[i] = (const float4*)(X + ((size_t)bi * SS + g_src[bi * SS + pi]) * HH);
    }

    float4 c0 = xp[0][lane];
    float4 c1 = xp[1][lane];
    float4 c2 = xp[2][lane];
    float4 c3 = xp[3][lane];

    float acc[4][LL];
#pragma unroll
    for (int i = 0; i < 4; i++)
#pragma unroll
        for (int j = 0; j < LL; j++) acc[i][j] = 0.f;

#pragma unroll
    for (int it = 0; it < HH / 128; it++) {   // 6 iterations, 16B/lane each
        const int k4 = it * 32 + lane;
        float4 n0, n1, n2, n3;
        if (it < HH / 128 - 1) {              // prefetch next iteration (8 in flight)
            const int kn = k4 + 32;
            n0 = xp[0][kn]; n1 = xp[1][kn]; n2 = xp[2][kn]; n3 = xp[3][kn];
        }
#pragma unroll
        for (int j = 0; j < LL; j++) {
            const float4 w = *(const float4*)(sWt + j * HH + k4 * 4);
            acc[0][j] += c0.x * w.x + c0.y * w.y + c0.z * w.z + c0.w * w.w;
            acc[1][j] += c1.x * w.x + c1.y * w.y + c1.z * w.z + c1.w * w.w;
            acc[2][j] += c2.x * w.x + c2.y * w.y + c2.z * w.z + c2.w * w.w;
            acc[3][j] += c3.x * w.x + c3.y * w.y + c3.z * w.z + c3.w * w.w;
        }
        if (it < HH / 128 - 1) { c0 = n0; c1 = n1; c2 = n2; c3 = n3; }
    }

    // warp reduction: every lane ends with the full sums
#pragma unroll
    for (int i = 0; i < 4; i++)
#pragma unroll
        for (int j = 0; j < LL; j++) {
            float u = acc[i][j];
            u += __shfl_xor_sync(0xffffffffu, u, 16);
            u += __shfl_xor_sync(0xffffffffu, u, 8);
            u += __shfl_xor_sync(0xffffffffu, u, 4);
            u += __shfl_xor_sync(0xffffffffu, u, 2);
            u += __shfl_xor_sync(0xffffffffu, u, 1);
            acc[i][j] = u;
        }

#pragma unroll
    for (int i = 0; i < 4; i++) {
        if (i < nv) {
            float l[LL];
            float mx = -1e30f;
#pragma unroll
            for (int j = 0; j < LL; j++) { l[j] = acc[i][j] + sB[j]; mx = fmaxf(mx, l[j]); }
            float sum = 0.f;
#pragma unroll
            for (int j = 0; j < LL; j++) { l[j] = __expf(l[j] - mx); sum += l[j]; }
            const float inv = 1.f / sum;
            if (lane < LL) out[(size_t)(t0 + i) * LL + lane] = l[lane] * inv;
        } else {
            if (lane < LL) out[(size_t)(t0 + i) * LL + lane] = g_sb[lane];
        }
    }
}

// ---------------------------------------------------------------------------
extern "C" void kernel_launch(void* const* d_in, const int* in_sizes, int n_in,
                              void* d_out, int out_size) {
    const float* seq  = nullptr;  // [64,512,768] f32
    const int*   mask = nullptr;  // [64,512]     i32
    const float* W    = nullptr;  // [768,9]      f32
    const float* bias = nullptr;  // [9]          f32
    for (int i = 0; i < n_in; i++) {
        switch (in_sizes[i]) {
            case BB * SS * HH: seq  = (const float*)d_in[i]; break;
            case BB * SS:      mask = (const int*)d_in[i];   break;
            case HH * LL:      W    = (const float*)d_in[i]; break;
            case LL:           bias = (const float*)d_in[i]; break;
        }
    }
    float* out = (float*)d_out;

    ner_scan_kernel<<<BB, SS>>>(mask, W, bias);                // scan + W^T + g_sb
    ner_main_kernel<<<(BB * SS) / 32, 256>>>(seq, bias, out);  // 1024 blocks
}

// round 14
// speedup vs baseline: 1.0366x; 1.0366x over previous
#include <cuda_runtime.h>
#include <cuda_pipeline.h>
#include <math.h>

#define BB 64
#define SS 512
#define HH 768
#define LL 9

#define W_BYTES   (LL * HH * 4)            // 27648
#define RING_OFF  W_BYTES                  // ring starts after W
#define STAGE_BYTES 2048                   // 4 tokens * 512 B
#define RING_WARP (4 * STAGE_BYTES)        // 4 stages per warp = 8192
#define RING_BYTES (8 * RING_WARP)         // 8 warps = 65536
#define SB_OFF    (RING_OFF + RING_BYTES)  // 93184
#define SMEM_TOTAL (SB_OFF + 64)           // 93248

// scratch (no allocations allowed in kernel_launch)
__device__ int   g_src[BB * SS];   // g_src[b*SS + p] = source token s for compacted slot p
__device__ int   g_cnt[BB];        // valid tokens per row
__device__ float g_sb[LL];         // softmax(bias) for tail slots
__device__ float g_Wt[LL * HH];    // W transposed: g_Wt[j*HH + k] = W[k*LL + j]

// ---------------------------------------------------------------------------
// Kernel 1: per-row ballot scan -> gather idx + count; W transpose; g_sb.
// ---------------------------------------------------------------------------
__global__ void __launch_bounds__(SS) ner_scan_kernel(const int* __restrict__ mask,
                                                      const float* __restrict__ W,
                                                      const float* __restrict__ bias) {
    __shared__ int wsum[16];
    const int b    = blockIdx.x;
    const int s    = threadIdx.x;
    const int lane = s & 31;
    const int wid  = s >> 5;
    const int m    = mask[b * SS + s];
    const unsigned bal = __ballot_sync(0xffffffffu, m != 0);
    const int pre  = __popc(bal & ((1u << lane) - 1u));
    if (lane == 31) wsum[wid] = __popc(bal);

    if (s < 108) {                          // W transpose slice
        const int idx = b * 108 + s;
        const int k = idx / LL;
        const int j = idx - k * LL;
        g_Wt[j * HH + k] = W[idx];
    }

    __syncthreads();
    if (wid == 0 && lane < 16) {
        int v = wsum[lane];
#pragma unroll
        for (int off = 1; off < 16; off <<= 1) {
            int u = __shfl_up_sync(0xffffu, v, off);
            if (lane >= off) v += u;
        }
        wsum[lane] = v;
    }
    __syncthreads();
    const int offset = wid ? wsum[wid - 1] : 0;
    if (m) g_src[b * SS + offset + pre] = s;
    if (s == 0) g_cnt[b] = wsum[15];

    if (b == 0 && s == 0) {
        float t[LL];
        float mx = -1e30f;
#pragma unroll
        for (int j = 0; j < LL; j++) { t[j] = bias[j]; mx = fmaxf(mx, t[j]); }
        float sum = 0.f;
#pragma unroll
        for (int j = 0; j < LL; j++) { t[j] = __expf(t[j] - mx); sum += t[j]; }
        const float inv = 1.f / sum;
#pragma unroll
        for (int j = 0; j < LL; j++) g_sb[j] = t[j] * inv;
    }
}

// ---------------------------------------------------------------------------
// Kernel 2: 32 slots/block (one row), 8 warps x 4 tokens. cp.async 4-stage
// smem ring per warp keeps ~6KB/warp of X in flight with zero register cost.
// Dead blocks / tail warps write softmax(bias) and exit.
// ---------------------------------------------------------------------------
__global__ void __launch_bounds__(256, 2) ner_main_kernel(const float* __restrict__ X,
                                                          const float* __restrict__ bias,
                                                          float* __restrict__ out) {
    extern __shared__ char smem[];
    float* sWt = (float*)smem;
    float* sB  = (float*)(smem + SB_OFF);

    const int tid  = threadIdx.x;
    const int lane = tid & 31;
    const int tb   = blockIdx.x * 32;
    const int bi   = tb >> 9;            // SS = 512
    const int pb   = tb & (SS - 1);
    const int cnt  = g_cnt[bi];

    if (pb >= cnt) {                     // whole block is tail (block-uniform)
        float* base = out + (size_t)tb * LL;
        for (int i = tid; i < 32 * LL; i += 256) base[i] = g_sb[i % LL];
        return;
    }

    {
        const float4* src = (const float4*)g_Wt;
        float4* dst = (float4*)sWt;
        for (int i = tid; i < (LL * HH) / 4; i += 256) dst[i] = src[i];
        if (tid < LL) sB[tid] = bias[tid];
    }
    __syncthreads();

    const int warp = tid >> 5;
    const int t0   = tb + warp * 4;
    const int p0   = t0 & (SS - 1);

    if (p0 >= cnt) {                     // tail warp in a mixed block
        float* base = out + (size_t)t0 * LL;
        for (int i = lane; i < 4 * LL; i += 32) base[i] = g_sb[i % LL];
        return;
    }

    const int nv = min(4, cnt - p0);
    const float4* xp[4];
#pragma unroll
    for (int i = 0; i < 4; i++) {
        const int pi = p0 + ((i < nv) ? i : 0);   // clamp (writes guarded later)
        xp[i] = (const float4*)(X + ((size_t)bi * SS + g_src[bi * SS + pi]) * HH);
    }

    char* ring = smem + RING_OFF + warp * RING_WARP;   // 4 stages x 2KB

    // prologue: issue stages 0..2 (12 cp.async of 16B per lane)
#pragma unroll
    for (int s = 0; s < 3; s++) {
#pragma unroll
        for (int i = 0; i < 4; i++)
            __pipeline_memcpy_async(ring + s * STAGE_BYTES + i * 512 + lane * 16,
                                    xp[i] + s * 32 + lane, 16);
        __pipeline_commit();
    }

    float acc[4][LL];
#pragma unroll
    for (int i = 0; i < 4; i++)
#pragma unroll
        for (int j = 0; j < LL; j++) acc[i][j] = 0.f;

#pragma unroll
    for (int it = 0; it < 6; it++) {
        if (it + 3 < 6) {                  // issue stage it+3 into slot (it+3)&3
#pragma unroll
            for (int i = 0; i < 4; i++)
                __pipeline_memcpy_async(ring + ((it + 3) & 3) * STAGE_BYTES + i * 512 + lane * 16,
                                        xp[i] + (it + 3) * 32 + lane, 16);
        }
        __pipeline_commit();               // one group per iteration (may be empty)
        __pipeline_wait_prior(3);          // stage `it` guaranteed complete

        const char* st = ring + (it & 3) * STAGE_BYTES + lane * 16;
        const float4 c0 = *(const float4*)(st);
        const float4 c1 = *(const float4*)(st + 512);
        const float4 c2 = *(const float4*)(st + 1024);
        const float4 c3 = *(const float4*)(st + 1536);

        const int k4 = it * 32 + lane;
#pragma unroll
        for (int j = 0; j < LL; j++) {
            const float4 w = *(const float4*)(sWt + j * HH + k4 * 4);
            acc[0][j] += c0.x * w.x + c0.y * w.y + c0.z * w.z + c0.w * w.w;
            acc[1][j] += c1.x * w.x + c1.y * w.y + c1.z * w.z + c1.w * w.w;
            acc[2][j] += c2.x * w.x + c2.y * w.y + c2.z * w.z + c2.w * w.w;
            acc[3][j] += c3.x * w.x + c3.y * w.y + c3.z * w.z + c3.w * w.w;
        }
    }

    // warp reduction: every lane ends with the full sums
#pragma unroll
    for (int i = 0; i < 4; i++)
#pragma unroll
        for (int j = 0; j < LL; j++) {
            float u = acc[i][j];
            u += __shfl_xor_sync(0xffffffffu, u, 16);
            u += __shfl_xor_sync(0xffffffffu, u, 8);
            u += __shfl_xor_sync(0xffffffffu, u, 4);
            u += __shfl_xor_sync(0xffffffffu, u, 2);
            u += __shfl_xor_sync(0xffffffffu, u, 1);
            acc[i][j] = u;
        }

#pragma unroll
    for (int i = 0; i < 4; i++) {
        if (i < nv) {
            float l[LL];
            float mx = -1e30f;
#pragma unroll
            for (int j = 0; j < LL; j++) { l[j] = acc[i][j] + sB[j]; mx = fmaxf(mx, l[j]); }
            float sum = 0.f;
#pragma unroll
            for (int j = 0; j < LL; j++) { l[j] = __expf(l[j] - mx); sum += l[j]; }
            const float inv = 1.f / sum;
            if (lane < LL) out[(size_t)(t0 + i) * LL + lane] = l[lane] * inv;
        } else {
            if (lane < LL) out[(size_t)(t0 + i) * LL + lane] = g_sb[lane];
        }
    }
}

// ---------------------------------------------------------------------------
extern "C" void kernel_launch(void* const* d_in, const int* in_sizes, int n_in,
                              void* d_out, int out_size) {
    const float* seq  = nullptr;  // [64,512,768] f32
    const int*   mask = nullptr;  // [64,512]     i32
    const float* W    = nullptr;  // [768,9]      f32
    const float* bias = nullptr;  // [9]          f32
    for (int i = 0; i < n_in; i++) {
        switch (in_sizes[i]) {
            case BB * SS * HH: seq  = (const float*)d_in[i]; break;
            case BB * SS:      mask = (const int*)d_in[i];   break;
            case HH * LL:      W    = (const float*)d_in[i]; break;
            case LL:           bias = (const float*)d_in[i]; break;
        }
    }
    float* out = (float*)d_out;

    cudaFuncSetAttribute(ner_main_kernel,
                         cudaFuncAttributeMaxDynamicSharedMemorySize, SMEM_TOTAL);

    ner_scan_kernel<<<BB, SS>>>(mask, W, bias);
    ner_main_kernel<<<(BB * SS) / 32, 256, SMEM_TOTAL>>>(seq, bias, out);
}